// round 10
// baseline (speedup 1.0000x reference)
#include <cuda_runtime.h>
#include <cstdint>
#include <cstddef>

#define SEQ   2048
#define BATCH 64
#define DIN   512
#define HID   512
#define NBLK  128
#define NTHR  512
#define UNITS 4
#define NR    16

#define WST   1032        // W row stride in floats (258 atoms ≡ 2 mod 8 -> conflict-free)
#define ABST  264         // A buffer row stride in floats (66 atoms ≡ 2 mod 8)
#define PST   20          // psm row stride (floats)

// shared layout (float offsets)
#define SM_W   0
#define SM_A0  (16*WST)                 // chunk buffer 0: [64][ABST]
#define SM_A1  (SM_A0 + 64*ABST)        // chunk buffer 1
#define SM_P   (SM_A1 + 64*ABST)        // psm [4][64][PST]
#define SM_B   (SM_P + 4*64*PST)        // bias [16]
#define SM_C   (SM_B + 16)              // cell [256]
#define SM_MB  (SM_C + 256)             // 2 mbarriers (8B each); byte off 8-aligned
#define SM_TOT (SM_MB + 4)
#define SMEM_BYTES (SM_TOT*4)           // 222,800 B

// ---- persistent scratch (no allocs) ----
__device__ float             g_h[2][BATCH * HID];   // ping-pong hidden state
__device__ volatile unsigned g_flags[NBLK * 64];    // one flag per block, 256B stride
__device__ unsigned          g_done;

// ---- helpers ----
__device__ __forceinline__ void fma2(unsigned long long& acc,
                                     unsigned long long a,
                                     unsigned long long b) {
    asm volatile("fma.rn.f32x2 %0, %1, %2, %0;" : "+l"(acc) : "l"(a), "l"(b));
}
__device__ __forceinline__ float2 unpk(unsigned long long v) {
    float2 f;
    asm("mov.b64 {%0, %1}, %2;" : "=f"(f.x), "=f"(f.y) : "l"(v));
    return f;
}
__device__ __forceinline__ float sigmoidf_(float x) { return 1.0f / (1.0f + __expf(-x)); }

__device__ __forceinline__ void mbar_init(uint32_t mbar, unsigned cnt) {
    asm volatile("mbarrier.init.shared.b64 [%0], %1;" :: "r"(mbar), "r"(cnt) : "memory");
}
__device__ __forceinline__ void stage_row_1k(uint32_t dst, const float* src, uint32_t mbar) {
    asm volatile("mbarrier.arrive.expect_tx.shared::cta.b64 _, [%0], %1;"
                 :: "r"(mbar), "r"(1024u) : "memory");
    asm volatile("cp.async.bulk.shared::cluster.global.mbarrier::complete_tx::bytes "
                 "[%0], [%1], %2, [%3];"
                 :: "r"(dst), "l"(src), "r"(1024u), "r"(mbar) : "memory");
}
__device__ __forceinline__ void mbar_wait(uint32_t mbar, unsigned parity) {
    unsigned done;
    asm volatile("{\n\t.reg .pred p;\n\t"
                 "mbarrier.try_wait.parity.acquire.cta.shared::cta.b64 p, [%1], %2;\n\t"
                 "selp.b32 %0, 1, 0, p;\n\t}"
                 : "=r"(done) : "r"(mbar), "r"(parity) : "memory");
    while (!done) {
        asm volatile("{\n\t.reg .pred p;\n\t"
                     "mbarrier.try_wait.parity.acquire.cta.shared::cta.b64 p, [%1], %2;\n\t"
                     "selp.b32 %0, 1, 0, p;\n\t}"
                     : "=r"(done) : "r"(mbar), "r"(parity) : "memory");
    }
}

// One 64-float K-span (8 quads of 4 floats, khalf-interleaved at 16B granularity):
// per kq: 4 W-loads + 4 A-loads (each 8 distinct 16B-phases/warp -> 1 cyc), 32 fma2.
#define CHUNK_FMA(WB, AB)                                                      \
    _Pragma("unroll")                                                          \
    for (int kq = 0; kq < 8; ++kq) {                                           \
        ulonglong2 w0 = *(const ulonglong2*)((WB) + 0 * 4 * WST  + kq * 8);    \
        ulonglong2 w1 = *(const ulonglong2*)((WB) + 1 * 4 * WST  + kq * 8);    \
        ulonglong2 w2 = *(const ulonglong2*)((WB) + 2 * 4 * WST  + kq * 8);    \
        ulonglong2 w3 = *(const ulonglong2*)((WB) + 3 * 4 * WST  + kq * 8);    \
        ulonglong2 b0 = *(const ulonglong2*)((AB) + 0 * 4 * ABST + kq * 8);    \
        ulonglong2 b1 = *(const ulonglong2*)((AB) + 1 * 4 * ABST + kq * 8);    \
        ulonglong2 b2 = *(const ulonglong2*)((AB) + 2 * 4 * ABST + kq * 8);    \
        ulonglong2 b3 = *(const ulonglong2*)((AB) + 3 * 4 * ABST + kq * 8);    \
        fma2(ac[0][0], b0.x, w0.x); fma2(ac[0][0], b0.y, w0.y);                \
        fma2(ac[0][1], b1.x, w0.x); fma2(ac[0][1], b1.y, w0.y);                \
        fma2(ac[0][2], b2.x, w0.x); fma2(ac[0][2], b2.y, w0.y);                \
        fma2(ac[0][3], b3.x, w0.x); fma2(ac[0][3], b3.y, w0.y);                \
        fma2(ac[1][0], b0.x, w1.x); fma2(ac[1][0], b0.y, w1.y);                \
        fma2(ac[1][1], b1.x, w1.x); fma2(ac[1][1], b1.y, w1.y);                \
        fma2(ac[1][2], b2.x, w1.x); fma2(ac[1][2], b2.y, w1.y);                \
        fma2(ac[1][3], b3.x, w1.x); fma2(ac[1][3], b3.y, w1.y);                \
        fma2(ac[2][0], b0.x, w2.x); fma2(ac[2][0], b0.y, w2.y);                \
        fma2(ac[2][1], b1.x, w2.x); fma2(ac[2][1], b1.y, w2.y);                \
        fma2(ac[2][2], b2.x, w2.x); fma2(ac[2][2], b2.y, w2.y);                \
        fma2(ac[2][3], b3.x, w2.x); fma2(ac[2][3], b3.y, w2.y);                \
        fma2(ac[3][0], b0.x, w3.x); fma2(ac[3][0], b0.y, w3.y);                \
        fma2(ac[3][1], b1.x, w3.x); fma2(ac[3][1], b1.y, w3.y);                \
        fma2(ac[3][2], b2.x, w3.x); fma2(ac[3][2], b2.y, w3.y);                \
        fma2(ac[3][3], b3.x, w3.x); fma2(ac[3][3], b3.y, w3.y);                \
    }

__global__ void __launch_bounds__(NTHR, 1)
lstm_kernel(const float* __restrict__ x,
            const float* __restrict__ Wf_, const float* __restrict__ bf_,
            const float* __restrict__ Wi_, const float* __restrict__ bi_,
            const float* __restrict__ Wg_, const float* __restrict__ bg_,
            const float* __restrict__ Wo_, const float* __restrict__ bo_,
            float* __restrict__ out)
{
    extern __shared__ float smem[];
    float* Wsm = smem + SM_W;
    float* A0  = smem + SM_A0;
    float* A1  = smem + SM_A1;
    float* psm = smem + SM_P;
    float* bsm = smem + SM_B;
    float* csm = smem + SM_C;

    const int tid = threadIdx.x;
    const int bid = blockIdx.x;
    const int j0  = bid * UNITS;

    const uint32_t a0_u32 = (uint32_t)__cvta_generic_to_shared(A0);
    const uint32_t a1_u32 = (uint32_t)__cvta_generic_to_shared(A1);
    const uint32_t mb0    = (uint32_t)__cvta_generic_to_shared(smem + SM_MB);
    const uint32_t mb1    = mb0 + 8;

    // ---- init: weights/bias to smem, h0/c0 zero, mbarriers ----
    {
        const float* Wptr[4] = { Wf_, Wi_, Wg_, Wo_ };
        for (int idx = tid; idx < 16 * 256; idx += NTHR) {   // 16 rows x 256 float4
            int rr = idx >> 8;
            int c4 = idx & 255;
            int u = rr >> 2, gg = rr & 3;
            const float4* src = (const float4*)(Wptr[gg] + (size_t)(j0 + u) * 1024);
            *(float4*)(Wsm + rr * WST + c4 * 4) = src[c4];
        }
        if (tid < NR) {
            int u = tid >> 2, gg = tid & 3;
            const float* bp = (gg == 0) ? bf_ : (gg == 1) ? bi_ : (gg == 2) ? bg_ : bo_;
            bsm[tid] = bp[j0 + u];
        }
        if (tid < 256) {
            csm[tid] = 0.0f;
            int b = tid & 63, u = tid >> 6;
            g_h[0][b * HID + j0 + u] = 0.0f;
            __threadfence();                 // writer-side release
        }
        if (tid == 0) { mbar_init(mb0, 64); mbar_init(mb1, 64); }
    }
    __syncthreads();

    const bool stager = ((tid & 7) == 0);   // 64 stagers, spread across warps
    const int  srow   = tid >> 3;           // staged batch row 0..63
    const uint32_t d0 = a0_u32 + (uint32_t)srow * (ABST * 4);
    const uint32_t d1 = a1_u32 + (uint32_t)srow * (ABST * 4);

    // prologue: stage step-0 x chunks; publish h0 flag
    if (stager) {
        const float* xr = x + (size_t)srow * 512;
        stage_row_1k(d0, xr,       mb0);    // x cols [0,256)
        stage_row_1k(d1, xr + 256, mb1);    // x cols [256,512)
    }
    if (tid == 0) {
        __threadfence();
        g_flags[bid * 64] = 1u;             // "h0 slice visible"
    }

    // ---- GEMM thread decomposition: splitK 4 x khalf 2, 4 rows x 4 batches ----
    const int g      = tid >> 7;         // K-quarter within chunk (64 floats)
    const int wb     = (tid >> 5) & 3;   // warp within group
    const int lane   = tid & 31;
    const int khalf  = lane >> 4;        // 16B-interleaved K-half within quarter
    const int rgroup = (lane >> 2) & 3;  // rows rgroup + 4*i
    const int bsub   = lane & 3;         // batches wb*16 + bsub + 4*j

    const float* wbase0 = Wsm + rgroup * WST + g * 64 + khalf * 4;
    const int    arow   = wb * 16 + bsub;

    for (int t = 0; t < SEQ; ++t) {
        const int p = t & 1;
        const float* __restrict__ hprev = g_h[p];
        const float* __restrict__ xnext = x + (size_t)(t + 1) * BATCH * DIN;

        unsigned long long ac[4][4];
        #pragma unroll
        for (int i = 0; i < 4; ++i)
            #pragma unroll
            for (int j = 0; j < 4; ++j) ac[i][j] = 0ull;

        const float* ab0 = A0 + (size_t)arow * ABST + g * 64 + khalf * 4;
        const float* ab1 = A1 + (size_t)arow * ABST + g * 64 + khalf * 4;

        // chunk 0 : x[0,256)   (staged last step / prologue; 2 completions/step -> parity const)
        mbar_wait(mb0, 0);
        CHUNK_FMA(wbase0, ab0)
        // overlap flag propagation with chunk-0 compute just done
        if (tid < 128) {
            const unsigned target = (unsigned)(t + 1);
            while (g_flags[tid * 64] < target) { }
        }
        __threadfence();                   // consumer-side acquire
        __syncthreads();                   // chunk0 consumed + flags observed
        if (stager) stage_row_1k(d0, hprev + (size_t)srow * 512, mb0);       // h[0,256)

        // chunk 1 : x[256,512)
        mbar_wait(mb1, 0);
        CHUNK_FMA(wbase0 + 256, ab1)
        __syncthreads();                   // chunk1 consumed
        if (stager) stage_row_1k(d1, hprev + (size_t)srow * 512 + 256, mb1); // h[256,512)

        // chunk 2 : h[0,256)
        mbar_wait(mb0, 1);
        CHUNK_FMA(wbase0 + 512, ab0)
        __syncthreads();                   // chunk2 consumed
        if (stager && t + 1 < SEQ)
            stage_row_1k(d0, xnext + (size_t)srow * 512, mb0);               // next x[0,256)

        // chunk 3 : h[256,512)
        mbar_wait(mb1, 1);
        CHUNK_FMA(wbase0 + 768, ab1)

        // ---- fold khalf (shfl) + write partial sums ----
        {
            #pragma unroll
            for (int i = 0; i < 4; ++i) {
                #pragma unroll
                for (int j = 0; j < 4; ++j) {
                    float2 v = unpk(ac[i][j]);
                    float  s = v.x + v.y;
                    s += __shfl_xor_sync(0xffffffffu, s, 16);
                    if (khalf == 0)
                        psm[(size_t)(g * 64 + arow + 4 * j) * PST + rgroup + 4 * i] = s;
                }
            }
        }
        __syncthreads();                   // chunk3 consumed + psm visible

        if (stager && t + 1 < SEQ)
            stage_row_1k(d1, xnext + (size_t)srow * 512 + 256, mb1);         // next x[256,512)

        // ---- epilogue: gates -> (h, c); publish h ----
        if (tid < 256) {
            int b = tid & 63, u = tid >> 6;
            float pre[4];
            #pragma unroll
            for (int gg = 0; gg < 4; ++gg) {
                int r = u * 4 + gg;
                pre[gg] = bsm[r]
                        + psm[(0 * 64 + b) * PST + r]
                        + psm[(1 * 64 + b) * PST + r]
                        + psm[(2 * 64 + b) * PST + r]
                        + psm[(3 * 64 + b) * PST + r];
            }
            float fg  = sigmoidf_(pre[0]);
            float ig  = sigmoidf_(pre[1]);
            float gg2 = tanhf(pre[2]);
            float og  = sigmoidf_(pre[3]);
            float c   = fg * csm[tid] + ig * gg2;
            csm[tid]  = c;
            float h   = og * tanhf(c);
            g_h[p ^ 1][b * HID + j0 + u] = h;
            out[((size_t)t * BATCH + b) * HID + j0 + u] = h;
            if (t == SEQ - 1) {
                size_t base = (size_t)SEQ * BATCH * HID;
                out[base + (size_t)b * HID + j0 + u] = h;
                out[base + (size_t)BATCH * HID + (size_t)b * HID + j0 + u] = c;
            }
            __threadfence();               // writer-side release
        }
        __syncthreads();
        if (tid == 0) {
            __threadfence();               // signaler-side release
            g_flags[bid * 64] = (unsigned)(t + 2);
        }
    }

    // ---- reset persistent state for the next graph replay ----
    __syncthreads();
    if (tid == 0) {
        __threadfence();
        if (atomicAdd(&g_done, 1u) == NBLK - 1) {
            g_done = 0u;
            for (int i = 0; i < NBLK; ++i) g_flags[i * 64] = 0u;
            __threadfence();
        }
    }
}

extern "C" void kernel_launch(void* const* d_in, const int* in_sizes, int n_in,
                              void* d_out, int out_size)
{
    const float* x  = (const float*)d_in[0];
    const float* Wf = (const float*)d_in[1];
    const float* bf = (const float*)d_in[2];
    const float* Wi = (const float*)d_in[3];
    const float* bi = (const float*)d_in[4];
    const float* Wg = (const float*)d_in[5];
    const float* bg = (const float*)d_in[6];
    const float* Wo = (const float*)d_in[7];
    const float* bo = (const float*)d_in[8];
    float* out = (float*)d_out;

    cudaFuncSetAttribute(lstm_kernel,
                         cudaFuncAttributeMaxDynamicSharedMemorySize, SMEM_BYTES);
    lstm_kernel<<<NBLK, NTHR, SMEM_BYTES>>>(x, Wf, bf, Wi, bi, Wg, bg, Wo, bo, out);
}

// round 11
// speedup vs baseline: 1.6492x; 1.6492x over previous
#include <cuda_runtime.h>
#include <cstdint>
#include <cstddef>

#define SEQ   2048
#define BATCH 64
#define DIN   512
#define HID   512
#define NBLK  128
#define NTHR  512
#define UNITS 4
#define NR    16

#define WST   1032        // W row stride in floats (258 atoms ≡ 2 mod 8 -> conflict-free)
#define ABST  264         // A buffer row stride in floats (66 atoms ≡ 2 mod 8)
#define PST   20          // psm row stride (floats)

// shared layout (float offsets)
#define SM_W   0
#define SM_A0  (16*WST)                 // chunk buffer 0: [64][ABST]
#define SM_A1  (SM_A0 + 64*ABST)        // chunk buffer 1
#define SM_P   (SM_A1 + 64*ABST)        // psm [4][64][PST]
#define SM_B   (SM_P + 4*64*PST)        // bias [16]
#define SM_C   (SM_B + 16)              // cell [256]
#define SM_MB  (SM_C + 256)             // 2 mbarriers (8B each); byte off 8-aligned
#define SM_TOT (SM_MB + 4)
#define SMEM_BYTES (SM_TOT*4)           // 222,800 B

// ---- persistent scratch (no allocs) ----
__device__ float    g_h[2][BATCH * HID];   // ping-pong hidden state
__device__ unsigned g_ctr;                 // monotonic step counter (NBLK adds/step)
__device__ unsigned g_done;

// ---- helpers ----
__device__ __forceinline__ void fma2(unsigned long long& acc,
                                     unsigned long long a,
                                     unsigned long long b) {
    asm volatile("fma.rn.f32x2 %0, %1, %2, %0;" : "+l"(acc) : "l"(a), "l"(b));
}
__device__ __forceinline__ float2 unpk(unsigned long long v) {
    float2 f;
    asm("mov.b64 {%0, %1}, %2;" : "=f"(f.x), "=f"(f.y) : "l"(v));
    return f;
}
__device__ __forceinline__ float sigmoidf_(float x) { return 1.0f / (1.0f + __expf(-x)); }

__device__ __forceinline__ void mbar_init(uint32_t mbar, unsigned cnt) {
    asm volatile("mbarrier.init.shared.b64 [%0], %1;" :: "r"(mbar), "r"(cnt) : "memory");
}
__device__ __forceinline__ void stage_row_1k(uint32_t dst, const float* src, uint32_t mbar) {
    asm volatile("mbarrier.arrive.expect_tx.shared::cta.b64 _, [%0], %1;"
                 :: "r"(mbar), "r"(1024u) : "memory");
    asm volatile("cp.async.bulk.shared::cluster.global.mbarrier::complete_tx::bytes "
                 "[%0], [%1], %2, [%3];"
                 :: "r"(dst), "l"(src), "r"(1024u), "r"(mbar) : "memory");
}
__device__ __forceinline__ void mbar_wait(uint32_t mbar, unsigned parity) {
    unsigned done;
    asm volatile("{\n\t.reg .pred p;\n\t"
                 "mbarrier.try_wait.parity.acquire.cta.shared::cta.b64 p, [%1], %2;\n\t"
                 "selp.b32 %0, 1, 0, p;\n\t}"
                 : "=r"(done) : "r"(mbar), "r"(parity) : "memory");
    while (!done) {
        asm volatile("{\n\t.reg .pred p;\n\t"
                     "mbarrier.try_wait.parity.acquire.cta.shared::cta.b64 p, [%1], %2;\n\t"
                     "selp.b32 %0, 1, 0, p;\n\t}"
                     : "=r"(done) : "r"(mbar), "r"(parity) : "memory");
    }
}
__device__ __forceinline__ unsigned ld_acq_gpu(const unsigned* p) {
    unsigned v;
    asm volatile("ld.acquire.gpu.global.u32 %0, [%1];" : "=r"(v) : "l"(p) : "memory");
    return v;
}
__device__ __forceinline__ void red_release_add(unsigned* p, unsigned v) {
    asm volatile("red.release.gpu.global.add.u32 [%0], %1;" :: "l"(p), "r"(v) : "memory");
}
__device__ __forceinline__ void stcs_f32(float* p, float v) {
    asm volatile("st.global.cs.f32 [%0], %1;" :: "l"(p), "f"(v));
}

// One 64-float K-span (8 quads), khalf-interleaved at 16B granularity:
// per kq: 4 W-loads + 4 A-loads (each 8 distinct 16B-phases/warp -> 1 cyc), 32 fma2.
#define CHUNK_FMA(WB, AB)                                                      \
    _Pragma("unroll")                                                          \
    for (int kq = 0; kq < 8; ++kq) {                                           \
        ulonglong2 w0 = *(const ulonglong2*)((WB) + 0 * 4 * WST  + kq * 8);    \
        ulonglong2 w1 = *(const ulonglong2*)((WB) + 1 * 4 * WST  + kq * 8);    \
        ulonglong2 w2 = *(const ulonglong2*)((WB) + 2 * 4 * WST  + kq * 8);    \
        ulonglong2 w3 = *(const ulonglong2*)((WB) + 3 * 4 * WST  + kq * 8);    \
        ulonglong2 b0 = *(const ulonglong2*)((AB) + 0 * 4 * ABST + kq * 8);    \
        ulonglong2 b1 = *(const ulonglong2*)((AB) + 1 * 4 * ABST + kq * 8);    \
        ulonglong2 b2 = *(const ulonglong2*)((AB) + 2 * 4 * ABST + kq * 8);    \
        ulonglong2 b3 = *(const ulonglong2*)((AB) + 3 * 4 * ABST + kq * 8);    \
        fma2(ac[0][0], b0.x, w0.x); fma2(ac[0][0], b0.y, w0.y);                \
        fma2(ac[0][1], b1.x, w0.x); fma2(ac[0][1], b1.y, w0.y);                \
        fma2(ac[0][2], b2.x, w0.x); fma2(ac[0][2], b2.y, w0.y);                \
        fma2(ac[0][3], b3.x, w0.x); fma2(ac[0][3], b3.y, w0.y);                \
        fma2(ac[1][0], b0.x, w1.x); fma2(ac[1][0], b0.y, w1.y);                \
        fma2(ac[1][1], b1.x, w1.x); fma2(ac[1][1], b1.y, w1.y);                \
        fma2(ac[1][2], b2.x, w1.x); fma2(ac[1][2], b2.y, w1.y);                \
        fma2(ac[1][3], b3.x, w1.x); fma2(ac[1][3], b3.y, w1.y);                \
        fma2(ac[2][0], b0.x, w2.x); fma2(ac[2][0], b0.y, w2.y);                \
        fma2(ac[2][1], b1.x, w2.x); fma2(ac[2][1], b1.y, w2.y);                \
        fma2(ac[2][2], b2.x, w2.x); fma2(ac[2][2], b2.y, w2.y);                \
        fma2(ac[2][3], b3.x, w2.x); fma2(ac[2][3], b3.y, w2.y);                \
        fma2(ac[3][0], b0.x, w3.x); fma2(ac[3][0], b0.y, w3.y);                \
        fma2(ac[3][1], b1.x, w3.x); fma2(ac[3][1], b1.y, w3.y);                \
        fma2(ac[3][2], b2.x, w3.x); fma2(ac[3][2], b2.y, w3.y);                \
        fma2(ac[3][3], b3.x, w3.x); fma2(ac[3][3], b3.y, w3.y);                \
    }

__global__ void __launch_bounds__(NTHR, 1)
lstm_kernel(const float* __restrict__ x,
            const float* __restrict__ Wf_, const float* __restrict__ bf_,
            const float* __restrict__ Wi_, const float* __restrict__ bi_,
            const float* __restrict__ Wg_, const float* __restrict__ bg_,
            const float* __restrict__ Wo_, const float* __restrict__ bo_,
            float* __restrict__ out)
{
    extern __shared__ float smem[];
    float* Wsm = smem + SM_W;
    float* A0  = smem + SM_A0;
    float* A1  = smem + SM_A1;
    float* psm = smem + SM_P;
    float* bsm = smem + SM_B;
    float* csm = smem + SM_C;

    const int tid = threadIdx.x;
    const int bid = blockIdx.x;
    const int j0  = bid * UNITS;

    const uint32_t a0_u32 = (uint32_t)__cvta_generic_to_shared(A0);
    const uint32_t a1_u32 = (uint32_t)__cvta_generic_to_shared(A1);
    const uint32_t mb0    = (uint32_t)__cvta_generic_to_shared(smem + SM_MB);
    const uint32_t mb1    = mb0 + 8;

    // ---- init: weights/bias to smem, h0/c0 zero, mbarriers ----
    {
        const float* Wptr[4] = { Wf_, Wi_, Wg_, Wo_ };
        for (int idx = tid; idx < 16 * 256; idx += NTHR) {   // 16 rows x 256 float4
            int rr = idx >> 8;
            int c4 = idx & 255;
            int u = rr >> 2, gg = rr & 3;
            const float4* src = (const float4*)(Wptr[gg] + (size_t)(j0 + u) * 1024);
            *(float4*)(Wsm + rr * WST + c4 * 4) = src[c4];
        }
        if (tid < NR) {
            int u = tid >> 2, gg = tid & 3;
            const float* bp = (gg == 0) ? bf_ : (gg == 1) ? bi_ : (gg == 2) ? bg_ : bo_;
            bsm[tid] = bp[j0 + u];
        }
        if (tid < 256) {
            csm[tid] = 0.0f;
            int b = tid & 63, u = tid >> 6;
            g_h[0][b * HID + j0 + u] = 0.0f;
            __threadfence();                 // writer-side release
        }
        if (tid == 0) { mbar_init(mb0, 64); mbar_init(mb1, 64); }
    }
    __syncthreads();

    const bool stager = ((tid & 7) == 0);   // 64 stagers, spread across warps
    const int  srow   = tid >> 3;           // staged batch row 0..63
    const uint32_t d0 = a0_u32 + (uint32_t)srow * (ABST * 4);
    const uint32_t d1 = a1_u32 + (uint32_t)srow * (ABST * 4);

    // prologue: stage step-0 x chunks; publish "h0 visible"
    if (stager) {
        const float* xr = x + (size_t)srow * 512;
        stage_row_1k(d0, xr,       mb0);    // x cols [0,256)
        stage_row_1k(d1, xr + 256, mb1);    // x cols [256,512)
    }
    if (tid == 0) red_release_add(&g_ctr, 1u);

    // ---- GEMM thread decomposition: splitK 4 x khalf 2, 4 rows x 4 batches ----
    const int g      = tid >> 7;         // K-quarter within chunk (64 floats)
    const int wb     = (tid >> 5) & 3;   // warp within group
    const int lane   = tid & 31;
    const int khalf  = lane >> 4;        // 16B-interleaved K-half within quarter
    const int rgroup = (lane >> 2) & 3;  // rows rgroup + 4*i
    const int bsub   = lane & 3;         // batches wb*16 + bsub + 4*j

    const float* wbase0 = Wsm + rgroup * WST + g * 64 + khalf * 4;
    const int    arow   = wb * 16 + bsub;

    for (int t = 0; t < SEQ; ++t) {
        const int p = t & 1;
        const float* __restrict__ hprev = g_h[p];
        const float* __restrict__ xnext = x + (size_t)(t + 1) * BATCH * DIN;

        unsigned long long ac[4][4];
        #pragma unroll
        for (int i = 0; i < 4; ++i)
            #pragma unroll
            for (int j = 0; j < 4; ++j) ac[i][j] = 0ull;

        const float* ab0 = A0 + (size_t)arow * ABST + g * 64 + khalf * 4;
        const float* ab1 = A1 + (size_t)arow * ABST + g * 64 + khalf * 4;

        // chunk 0 : x[0,256)   (staged last step / prologue; 2 flips/step -> const parity)
        mbar_wait(mb0, 0);
        CHUNK_FMA(wbase0, ab0)
        // single-line counter poll (warp 0 only) overlapped with chunk-0 compute above
        if (tid < 32) {
            const unsigned target = (unsigned)(t + 1) * NBLK;
            while (ld_acq_gpu(&g_ctr) < target) { }
        }
        __syncthreads();                   // chunk0 consumed + counter observed
        if (stager) stage_row_1k(d0, hprev + (size_t)srow * 512, mb0);       // h[0,256)

        // chunk 1 : x[256,512)
        mbar_wait(mb1, 0);
        CHUNK_FMA(wbase0 + 256, ab1)
        __syncthreads();                   // chunk1 consumed
        if (stager) stage_row_1k(d1, hprev + (size_t)srow * 512 + 256, mb1); // h[256,512)

        // chunk 2 : h[0,256)
        mbar_wait(mb0, 1);
        CHUNK_FMA(wbase0 + 512, ab0)
        __syncthreads();                   // chunk2 consumed
        if (stager && t + 1 < SEQ)
            stage_row_1k(d0, xnext + (size_t)srow * 512, mb0);               // next x[0,256)

        // chunk 3 : h[256,512)
        mbar_wait(mb1, 1);
        CHUNK_FMA(wbase0 + 768, ab1)

        // ---- fold khalf (shfl) + write partial sums ----
        {
            #pragma unroll
            for (int i = 0; i < 4; ++i) {
                #pragma unroll
                for (int j = 0; j < 4; ++j) {
                    float2 v = unpk(ac[i][j]);
                    float  s = v.x + v.y;
                    s += __shfl_xor_sync(0xffffffffu, s, 16);
                    if (khalf == 0)
                        psm[(size_t)(g * 64 + arow + 4 * j) * PST + rgroup + 4 * i] = s;
                }
            }
        }
        __syncthreads();                   // chunk3 consumed + psm visible

        if (stager && t + 1 < SEQ)
            stage_row_1k(d1, xnext + (size_t)srow * 512 + 256, mb1);         // next x[256,512)

        // ---- epilogue: gates -> (h, c); publish FIRST, then output stores ----
        float hv = 0.f, cv = 0.f;
        int   b = tid & 63, u = tid >> 6;
        if (tid < 256) {
            float pre[4];
            #pragma unroll
            for (int gg = 0; gg < 4; ++gg) {
                int r = u * 4 + gg;
                pre[gg] = bsm[r]
                        + psm[(0 * 64 + b) * PST + r]
                        + psm[(1 * 64 + b) * PST + r]
                        + psm[(2 * 64 + b) * PST + r]
                        + psm[(3 * 64 + b) * PST + r];
            }
            float fg  = sigmoidf_(pre[0]);
            float ig  = sigmoidf_(pre[1]);
            float gg2 = tanhf(pre[2]);
            float og  = sigmoidf_(pre[3]);
            cv        = fg * csm[tid] + ig * gg2;
            csm[tid]  = cv;
            hv        = og * tanhf(cv);
            g_h[p ^ 1][b * HID + j0 + u] = hv;   // the only cross-SM dependency
            __threadfence();                     // writer-side release
        }
        __syncthreads();
        if (tid == 0) red_release_add(&g_ctr, 1u);   // release: h_t visible

        // out stores off the inter-SM critical path
        if (tid < 256) {
            stcs_f32(&out[((size_t)t * BATCH + b) * HID + j0 + u], hv);
            if (t == SEQ - 1) {
                size_t base = (size_t)SEQ * BATCH * HID;
                stcs_f32(&out[base + (size_t)b * HID + j0 + u], hv);
                stcs_f32(&out[base + (size_t)BATCH * HID + (size_t)b * HID + j0 + u], cv);
            }
        }
    }

    // ---- reset persistent state for the next graph replay ----
    __syncthreads();
    if (tid == 0) {
        __threadfence();
        if (atomicAdd(&g_done, 1u) == NBLK - 1) {
            g_done = 0u;
            atomicExch(&g_ctr, 0u);
            __threadfence();
        }
    }
}

extern "C" void kernel_launch(void* const* d_in, const int* in_sizes, int n_in,
                              void* d_out, int out_size)
{
    const float* x  = (const float*)d_in[0];
    const float* Wf = (const float*)d_in[1];
    const float* bf = (const float*)d_in[2];
    const float* Wi = (const float*)d_in[3];
    const float* bi = (const float*)d_in[4];
    const float* Wg = (const float*)d_in[5];
    const float* bg = (const float*)d_in[6];
    const float* Wo = (const float*)d_in[7];
    const float* bo = (const float*)d_in[8];
    float* out = (float*)d_out;

    cudaFuncSetAttribute(lstm_kernel,
                         cudaFuncAttributeMaxDynamicSharedMemorySize, SMEM_BYTES);
    lstm_kernel<<<NBLK, NTHR, SMEM_BYTES>>>(x, Wf, bf, Wi, bi, Wg, bg, Wo, bo, out);
}

// round 12
// speedup vs baseline: 1.6513x; 1.0013x over previous
#include <cuda_runtime.h>
#include <cstdint>
#include <cstddef>

#define SEQ   2048
#define BATCH 64
#define DIN   512
#define HID   512
#define NBLK  128
#define NTHR  512
#define UNITS 4
#define NR    16

#define WST   1032        // W row stride in floats (258 atoms ≡ 2 mod 8 -> conflict-free)
#define ABST  264         // A buffer row stride in floats (66 atoms ≡ 2 mod 8)
#define PST   20          // psm row stride (floats)

// shared layout (float offsets)
#define SM_W   0
#define SM_A0  (16*WST)                 // chunk buffer 0: [64][ABST]
#define SM_A1  (SM_A0 + 64*ABST)        // chunk buffer 1
#define SM_P   (SM_A1 + 64*ABST)        // psm [4][64][PST]
#define SM_B   (SM_P + 4*64*PST)        // bias [16]
#define SM_C   (SM_B + 16)              // cell [256]
#define SM_MB  (SM_C + 256)             // 2 mbarriers (8B each); byte off 8-aligned
#define SM_TOT (SM_MB + 4)
#define SMEM_BYTES (SM_TOT*4)           // 222,800 B

// ---- persistent scratch (no allocs) ----
__device__ float    g_h[2][BATCH * HID];   // ping-pong hidden state
__device__ unsigned g_ctr;                 // monotonic step counter (NBLK adds/step)
__device__ unsigned g_done;

// ---- helpers ----
__device__ __forceinline__ void fma2(unsigned long long& acc,
                                     unsigned long long a,
                                     unsigned long long b) {
    asm volatile("fma.rn.f32x2 %0, %1, %2, %0;" : "+l"(acc) : "l"(a), "l"(b));
}
__device__ __forceinline__ float2 unpk(unsigned long long v) {
    float2 f;
    asm("mov.b64 {%0, %1}, %2;" : "=f"(f.x), "=f"(f.y) : "l"(v));
    return f;
}
__device__ __forceinline__ float sigmoidf_(float x) { return 1.0f / (1.0f + __expf(-x)); }

__device__ __forceinline__ void mbar_init(uint32_t mbar, unsigned cnt) {
    asm volatile("mbarrier.init.shared.b64 [%0], %1;" :: "r"(mbar), "r"(cnt) : "memory");
}
__device__ __forceinline__ void stage_row_1k(uint32_t dst, const float* src, uint32_t mbar) {
    asm volatile("mbarrier.arrive.expect_tx.shared::cta.b64 _, [%0], %1;"
                 :: "r"(mbar), "r"(1024u) : "memory");
    asm volatile("cp.async.bulk.shared::cluster.global.mbarrier::complete_tx::bytes "
                 "[%0], [%1], %2, [%3];"
                 :: "r"(dst), "l"(src), "r"(1024u), "r"(mbar) : "memory");
}
__device__ __forceinline__ void mbar_wait(uint32_t mbar, unsigned parity) {
    unsigned done;
    asm volatile("{\n\t.reg .pred p;\n\t"
                 "mbarrier.try_wait.parity.acquire.cta.shared::cta.b64 p, [%1], %2;\n\t"
                 "selp.b32 %0, 1, 0, p;\n\t}"
                 : "=r"(done) : "r"(mbar), "r"(parity) : "memory");
    while (!done) {
        asm volatile("{\n\t.reg .pred p;\n\t"
                     "mbarrier.try_wait.parity.acquire.cta.shared::cta.b64 p, [%1], %2;\n\t"
                     "selp.b32 %0, 1, 0, p;\n\t}"
                     : "=r"(done) : "r"(mbar), "r"(parity) : "memory");
    }
}
__device__ __forceinline__ unsigned ld_acq_gpu(const unsigned* p) {
    unsigned v;
    asm volatile("ld.acquire.gpu.global.u32 %0, [%1];" : "=r"(v) : "l"(p) : "memory");
    return v;
}
__device__ __forceinline__ void red_release_add(unsigned* p, unsigned v) {
    asm volatile("red.release.gpu.global.add.u32 [%0], %1;" :: "l"(p), "r"(v) : "memory");
}
__device__ __forceinline__ void stcs_f32(float* p, float v) {
    asm volatile("st.global.cs.f32 [%0], %1;" :: "l"(p), "f"(v));
}

// One 64-float K-span (8 quads), khalf-interleaved at 16B granularity:
// per kq: 4 W-loads + 4 A-loads (each 8 distinct 16B-phases/warp -> 1 cyc), 32 fma2.
#define CHUNK_FMA(WB, AB)                                                      \
    _Pragma("unroll")                                                          \
    for (int kq = 0; kq < 8; ++kq) {                                           \
        ulonglong2 w0 = *(const ulonglong2*)((WB) + 0 * 4 * WST  + kq * 8);    \
        ulonglong2 w1 = *(const ulonglong2*)((WB) + 1 * 4 * WST  + kq * 8);    \
        ulonglong2 w2 = *(const ulonglong2*)((WB) + 2 * 4 * WST  + kq * 8);    \
        ulonglong2 w3 = *(const ulonglong2*)((WB) + 3 * 4 * WST  + kq * 8);    \
        ulonglong2 b0 = *(const ulonglong2*)((AB) + 0 * 4 * ABST + kq * 8);    \
        ulonglong2 b1 = *(const ulonglong2*)((AB) + 1 * 4 * ABST + kq * 8);    \
        ulonglong2 b2 = *(const ulonglong2*)((AB) + 2 * 4 * ABST + kq * 8);    \
        ulonglong2 b3 = *(const ulonglong2*)((AB) + 3 * 4 * ABST + kq * 8);    \
        fma2(ac[0][0], b0.x, w0.x); fma2(ac[0][0], b0.y, w0.y);                \
        fma2(ac[0][1], b1.x, w0.x); fma2(ac[0][1], b1.y, w0.y);                \
        fma2(ac[0][2], b2.x, w0.x); fma2(ac[0][2], b2.y, w0.y);                \
        fma2(ac[0][3], b3.x, w0.x); fma2(ac[0][3], b3.y, w0.y);                \
        fma2(ac[1][0], b0.x, w1.x); fma2(ac[1][0], b0.y, w1.y);                \
        fma2(ac[1][1], b1.x, w1.x); fma2(ac[1][1], b1.y, w1.y);                \
        fma2(ac[1][2], b2.x, w1.x); fma2(ac[1][2], b2.y, w1.y);                \
        fma2(ac[1][3], b3.x, w1.x); fma2(ac[1][3], b3.y, w1.y);                \
        fma2(ac[2][0], b0.x, w2.x); fma2(ac[2][0], b0.y, w2.y);                \
        fma2(ac[2][1], b1.x, w2.x); fma2(ac[2][1], b1.y, w2.y);                \
        fma2(ac[2][2], b2.x, w2.x); fma2(ac[2][2], b2.y, w2.y);                \
        fma2(ac[2][3], b3.x, w2.x); fma2(ac[2][3], b3.y, w2.y);                \
        fma2(ac[3][0], b0.x, w3.x); fma2(ac[3][0], b0.y, w3.y);                \
        fma2(ac[3][1], b1.x, w3.x); fma2(ac[3][1], b1.y, w3.y);                \
        fma2(ac[3][2], b2.x, w3.x); fma2(ac[3][2], b2.y, w3.y);                \
        fma2(ac[3][3], b3.x, w3.x); fma2(ac[3][3], b3.y, w3.y);                \
    }

__global__ void __launch_bounds__(NTHR, 1)
lstm_kernel(const float* __restrict__ x,
            const float* __restrict__ Wf_, const float* __restrict__ bf_,
            const float* __restrict__ Wi_, const float* __restrict__ bi_,
            const float* __restrict__ Wg_, const float* __restrict__ bg_,
            const float* __restrict__ Wo_, const float* __restrict__ bo_,
            float* __restrict__ out)
{
    extern __shared__ float smem[];
    float* Wsm = smem + SM_W;
    float* A0  = smem + SM_A0;
    float* A1  = smem + SM_A1;
    float* psm = smem + SM_P;
    float* bsm = smem + SM_B;
    float* csm = smem + SM_C;

    const int tid = threadIdx.x;
    const int bid = blockIdx.x;
    const int j0  = bid * UNITS;

    const uint32_t a0_u32 = (uint32_t)__cvta_generic_to_shared(A0);
    const uint32_t a1_u32 = (uint32_t)__cvta_generic_to_shared(A1);
    const uint32_t mb0    = (uint32_t)__cvta_generic_to_shared(smem + SM_MB);
    const uint32_t mb1    = mb0 + 8;

    // ---- init: weights/bias to smem, h0/c0 zero, mbarriers ----
    {
        const float* Wptr[4] = { Wf_, Wi_, Wg_, Wo_ };
        for (int idx = tid; idx < 16 * 256; idx += NTHR) {   // 16 rows x 256 float4
            int rr = idx >> 8;
            int c4 = idx & 255;
            int u = rr >> 2, gg = rr & 3;
            const float4* src = (const float4*)(Wptr[gg] + (size_t)(j0 + u) * 1024);
            *(float4*)(Wsm + rr * WST + c4 * 4) = src[c4];
        }
        if (tid < NR) {
            int u = tid >> 2, gg = tid & 3;
            const float* bp = (gg == 0) ? bf_ : (gg == 1) ? bi_ : (gg == 2) ? bg_ : bo_;
            bsm[tid] = bp[j0 + u];
        }
        if (tid < 256) {
            csm[tid] = 0.0f;
            int b = tid & 63, u = tid >> 6;
            g_h[0][b * HID + j0 + u] = 0.0f;
            __threadfence();                 // writer-side release
        }
        if (tid == 0) { mbar_init(mb0, 64); mbar_init(mb1, 64); }
    }
    __syncthreads();

    const bool stager = ((tid & 7) == 0);   // 64 stagers, spread across warps
    const int  srow   = tid >> 3;           // staged batch row 0..63
    const uint32_t d0 = a0_u32 + (uint32_t)srow * (ABST * 4);
    const uint32_t d1 = a1_u32 + (uint32_t)srow * (ABST * 4);

    // prologue: stage step-0 x chunks; publish "h0 visible"
    if (stager) {
        const float* xr = x + (size_t)srow * 512;
        stage_row_1k(d0, xr,       mb0);    // x cols [0,256)
        stage_row_1k(d1, xr + 256, mb1);    // x cols [256,512)
    }
    if (tid == 0) red_release_add(&g_ctr, 1u);

    // ---- GEMM thread decomposition: splitK 4 x khalf 2, 4 rows x 4 batches ----
    const int g      = tid >> 7;         // K-quarter within chunk (64 floats)
    const int wb     = (tid >> 5) & 3;   // warp within group
    const int lane   = tid & 31;
    const int khalf  = lane >> 4;        // 16B-interleaved K-half within quarter
    const int rgroup = (lane >> 2) & 3;  // rows rgroup + 4*i
    const int bsub   = lane & 3;         // batches wb*16 + bsub + 4*j

    const float* wbase0 = Wsm + rgroup * WST + g * 64 + khalf * 4;
    const int    arow   = wb * 16 + bsub;

    for (int t = 0; t < SEQ; ++t) {
        const int p = t & 1;
        const float* __restrict__ hprev = g_h[p];
        const float* __restrict__ xnext = x + (size_t)(t + 1) * BATCH * DIN;

        unsigned long long ac[4][4];
        #pragma unroll
        for (int i = 0; i < 4; ++i)
            #pragma unroll
            for (int j = 0; j < 4; ++j) ac[i][j] = 0ull;

        const float* ab0 = A0 + (size_t)arow * ABST + g * 64 + khalf * 4;
        const float* ab1 = A1 + (size_t)arow * ABST + g * 64 + khalf * 4;

        // chunk 0 : x[0,256)   (staged last step / prologue; 2 flips/step -> const parity)
        mbar_wait(mb0, 0);
        CHUNK_FMA(wbase0, ab0)
        // single-line counter poll (warp 0 only) overlapped with chunk-0 compute above
        if (tid < 32) {
            const unsigned target = (unsigned)(t + 1) * NBLK;
            while (ld_acq_gpu(&g_ctr) < target) { }
        }
        __syncthreads();                   // chunk0 consumed + counter observed
        if (stager) stage_row_1k(d0, hprev + (size_t)srow * 512, mb0);       // h[0,256)

        // chunk 1 : x[256,512)
        mbar_wait(mb1, 0);
        CHUNK_FMA(wbase0 + 256, ab1)
        __syncthreads();                   // chunk1 consumed
        if (stager) stage_row_1k(d1, hprev + (size_t)srow * 512 + 256, mb1); // h[256,512)

        // chunk 2 : h[0,256)
        mbar_wait(mb0, 1);
        CHUNK_FMA(wbase0 + 512, ab0)
        __syncthreads();                   // chunk2 consumed
        if (stager && t + 1 < SEQ)
            stage_row_1k(d0, xnext + (size_t)srow * 512, mb0);               // next x[0,256)

        // chunk 3 : h[256,512)
        mbar_wait(mb1, 1);
        CHUNK_FMA(wbase0 + 768, ab1)

        // ---- fold khalf (shfl) + write partial sums ----
        {
            #pragma unroll
            for (int i = 0; i < 4; ++i) {
                #pragma unroll
                for (int j = 0; j < 4; ++j) {
                    float2 v = unpk(ac[i][j]);
                    float  s = v.x + v.y;
                    s += __shfl_xor_sync(0xffffffffu, s, 16);
                    if (khalf == 0)
                        psm[(size_t)(g * 64 + arow + 4 * j) * PST + rgroup + 4 * i] = s;
                }
            }
        }
        __syncthreads();                   // chunk3 consumed + psm visible

        if (stager && t + 1 < SEQ)
            stage_row_1k(d1, xnext + (size_t)srow * 512 + 256, mb1);         // next x[256,512)

        // ---- epilogue: gates -> (h, c); publish FIRST, then output stores ----
        float hv = 0.f, cv = 0.f;
        int   b = tid & 63, u = tid >> 6;
        if (tid < 256) {
            float pre[4];
            #pragma unroll
            for (int gg = 0; gg < 4; ++gg) {
                int r = u * 4 + gg;
                pre[gg] = bsm[r]
                        + psm[(0 * 64 + b) * PST + r]
                        + psm[(1 * 64 + b) * PST + r]
                        + psm[(2 * 64 + b) * PST + r]
                        + psm[(3 * 64 + b) * PST + r];
            }
            float fg  = sigmoidf_(pre[0]);
            float ig  = sigmoidf_(pre[1]);
            float gg2 = tanhf(pre[2]);
            float og  = sigmoidf_(pre[3]);
            cv        = fg * csm[tid] + ig * gg2;
            csm[tid]  = cv;
            hv        = og * tanhf(cv);
            g_h[p ^ 1][b * HID + j0 + u] = hv;   // the only cross-SM dependency
            __threadfence();                     // writer-side release
        }
        __syncthreads();
        if (tid == 0) red_release_add(&g_ctr, 1u);   // release: h_t visible

        // out stores off the inter-SM critical path
        if (tid < 256) {
            stcs_f32(&out[((size_t)t * BATCH + b) * HID + j0 + u], hv);
            if (t == SEQ - 1) {
                size_t base = (size_t)SEQ * BATCH * HID;
                stcs_f32(&out[base + (size_t)b * HID + j0 + u], hv);
                stcs_f32(&out[base + (size_t)BATCH * HID + (size_t)b * HID + j0 + u], cv);
            }
        }
    }

    // ---- reset persistent state for the next graph replay ----
    __syncthreads();
    if (tid == 0) {
        __threadfence();
        if (atomicAdd(&g_done, 1u) == NBLK - 1) {
            g_done = 0u;
            atomicExch(&g_ctr, 0u);
            __threadfence();
        }
    }
}

extern "C" void kernel_launch(void* const* d_in, const int* in_sizes, int n_in,
                              void* d_out, int out_size)
{
    const float* x  = (const float*)d_in[0];
    const float* Wf = (const float*)d_in[1];
    const float* bf = (const float*)d_in[2];
    const float* Wi = (const float*)d_in[3];
    const float* bi = (const float*)d_in[4];
    const float* Wg = (const float*)d_in[5];
    const float* bg = (const float*)d_in[6];
    const float* Wo = (const float*)d_in[7];
    const float* bo = (const float*)d_in[8];
    float* out = (float*)d_out;

    cudaFuncSetAttribute(lstm_kernel,
                         cudaFuncAttributeMaxDynamicSharedMemorySize, SMEM_BYTES);
    lstm_kernel<<<NBLK, NTHR, SMEM_BYTES>>>(x, Wf, bf, Wi, bi, Wg, bg, Wo, bo, out);
}